// round 15
// baseline (speedup 1.0000x reference)
#include <cuda_runtime.h>
#include <cuda_bf16.h>
#include <cstdint>

// Problem dims
#define H_   8
#define IN_  512
#define SEQ_ 1024
#define MID_ 2048

// ---------------- HMMA GEMM tile config ----------------
constexpr int BM = 128, BN = 128, BK = 32;     // BK in bf16 k-elements per stage
constexpr int RSB = 80;                        // smem row stride bytes (64 data + 16 pad)
constexpr int OPB = 128 * RSB;                 // bytes per operand-half tile (10240)
constexpr int OFF_AHI = 0, OFF_ALO = OPB, OFF_BHI = 2 * OPB, OFF_BLO = 3 * OPB;
constexpr int STAGE = 4 * OPB;                 // 40960
constexpr int GSMEM = 2 * STAGE;               // 81920 bytes dynamic smem

// ---------------- scratch (device globals; no allocation allowed) ----------------
__device__ float g_mout[IN_ * SEQ_];
__device__ float g_x2  [IN_ * SEQ_];
// activation split buffers
__device__ __nv_bfloat16 g_xT_h  [SEQ_ * IN_],           g_xT_l  [SEQ_ * IN_];
__device__ __nv_bfloat16 g_qkvS_h[3 * IN_ * SEQ_],       g_qkvS_l[3 * IN_ * SEQ_];
__device__ __nv_bfloat16 g_hbS_h [H_ * 3 * IN_ * MID_],  g_hbS_l [H_ * 3 * IN_ * MID_];
__device__ __nv_bfloat16 g_qkT_h [2 * H_ * SEQ_ * IN_],  g_qkT_l [2 * H_ * SEQ_ * IN_];
__device__ __nv_bfloat16 g_vS_h  [H_ * IN_ * SEQ_],      g_vS_l  [H_ * IN_ * SEQ_];
__device__ __nv_bfloat16 g_bTS_h [H_ * SEQ_ * SEQ_],     g_bTS_l [H_ * SEQ_ * SEQ_];
__device__ __nv_bfloat16 g_aT_h  [SEQ_ * H_ * IN_],      g_aT_l  [SEQ_ * H_ * IN_];
__device__ __nv_bfloat16 g_zT_h  [2 * SEQ_ * MID_],      g_zT_l  [2 * SEQ_ * MID_];
// per-block weight splits
__device__ __nv_bfloat16 g_wq1_h [3 * IN_ * IN_],        g_wq1_l [3 * IN_ * IN_];
__device__ __nv_bfloat16 g_wq2_h [3 * IN_ * IN_],        g_wq2_l [3 * IN_ * IN_];
__device__ __nv_bfloat16 g_W1a_h [H_ * 3 * MID_ * SEQ_], g_W1a_l [H_ * 3 * MID_ * SEQ_];
__device__ __nv_bfloat16 g_W1b_h [H_ * 3 * MID_ * SEQ_], g_W1b_l [H_ * 3 * MID_ * SEQ_];
__device__ __nv_bfloat16 g_W2a_h [H_ * 3 * SEQ_ * MID_], g_W2a_l [H_ * 3 * SEQ_ * MID_];
__device__ __nv_bfloat16 g_W2b_h [H_ * 3 * SEQ_ * MID_], g_W2b_l [H_ * 3 * SEQ_ * MID_];
__device__ __nv_bfloat16 g_c1a_h [MID_ * H_ * IN_],      g_c1a_l [MID_ * H_ * IN_];
__device__ __nv_bfloat16 g_c1b_h [MID_ * H_ * IN_],      g_c1b_l [MID_ * H_ * IN_];
__device__ __nv_bfloat16 g_c2a_h [IN_ * MID_],           g_c2a_l [IN_ * MID_];
__device__ __nv_bfloat16 g_c2b_h [IN_ * MID_],           g_c2b_l [IN_ * MID_];
// combined FFN weights (both heads contiguous -> z=2 batched GEMMs)
__device__ __nv_bfloat16 g_WaS_h [2 * MID_ * IN_],       g_WaS_l [2 * MID_ * IN_];
__device__ __nv_bfloat16 g_WbS_h [2 * IN_ * MID_],       g_WbS_l [2 * IN_ * MID_];

// ---------------- PTX helpers ----------------
__device__ __forceinline__ uint32_t smem_u32(const void* p) {
    uint32_t a;
    asm("{ .reg .u64 t; cvta.to.shared.u64 t, %1; cvt.u32.u64 %0, t; }" : "=r"(a) : "l"(p));
    return a;
}
__device__ __forceinline__ void cpa16(uint32_t d, const void* s) {
    asm volatile("cp.async.cg.shared.global [%0], [%1], 16;" :: "r"(d), "l"(s));
}
__device__ __forceinline__ void cp_commit() {
    asm volatile("cp.async.commit_group;" ::: "memory");
}
template<int N> __device__ __forceinline__ void cp_wait() {
    asm volatile("cp.async.wait_group %0;" :: "n"(N) : "memory");
}
__device__ __forceinline__ void ldsm4(uint32_t& r0, uint32_t& r1, uint32_t& r2, uint32_t& r3, uint32_t a) {
    asm volatile("ldmatrix.sync.aligned.m8n8.x4.shared.b16 {%0,%1,%2,%3}, [%4];"
                 : "=r"(r0), "=r"(r1), "=r"(r2), "=r"(r3) : "r"(a));
}
__device__ __forceinline__ void mma_bf16(float c[4], const uint32_t a[4], const uint32_t b[2]) {
    asm volatile(
        "mma.sync.aligned.m16n8k16.row.col.f32.bf16.bf16.f32 "
        "{%0,%1,%2,%3}, {%4,%5,%6,%7}, {%8,%9}, {%0,%1,%2,%3};\n"
        : "+f"(c[0]), "+f"(c[1]), "+f"(c[2]), "+f"(c[3])
        : "r"(a[0]), "r"(a[1]), "r"(a[2]), "r"(a[3]), "r"(b[0]), "r"(b[1]));
}
__device__ __forceinline__ uint32_t pack2(__nv_bfloat162 h) {
    return *reinterpret_cast<uint32_t*>(&h);
}

// ---------------- GEMM: C = act( A * B^T [+Res] ), operands pre-split bf16 hi/lo ----------------
// Single __syncthreads per k-tile:  wait -> sync -> stage(t+1) -> compute(t).
// OM=0: fp32 out (RO relu, RES residual; Res indexed WITHOUT z offset).
// OM=1: bf16 hi/lo split out, same layout.
// OM=2: bf16 hi/lo split out TRANSPOSED (row n, ld=ldt; RO relu).
// OM=4: qkv-combined — zc<2 writes transposed-split (Coh/Col, ld=ldt, off zh*sC1+zc*sC2);
//       zc==2 writes layout-split v (pointers smuggled via Cf/Res, off zh*sC1).
template<bool RO, bool RES, int OM>
__global__ void __launch_bounds__(256, 2)
gemm_hmma(const __nv_bfloat16* __restrict__ Ah, const __nv_bfloat16* __restrict__ Al,
          const __nv_bfloat16* __restrict__ Bh, const __nv_bfloat16* __restrict__ Bl,
          float* __restrict__ Cf, __nv_bfloat16* __restrict__ Coh, __nv_bfloat16* __restrict__ Col,
          const float* __restrict__ Res,
          int M, int N, int K, int ldt,
          long long sA1, long long sA2, long long sB1, long long sB2,
          long long sC1, long long sC2, int zdiv)
{
    extern __shared__ char smem[];
    const int tid = threadIdx.x, lane = tid & 31, warp = tid >> 5;

    const int zz = blockIdx.z, zh = zz / zdiv, zc = zz - zh * zdiv;
    const long long offA = zh * sA1 + (long long)zc * sA2;
    const long long offB = zh * sB1 + (long long)zc * sB2;
    const long long cOff = zh * sC1 + (long long)zc * sC2;

    const int bm = blockIdx.y * BM, bn = blockIdx.x * BN;
    const uint32_t sb = smem_u32(smem);

    const int srow = tid >> 2, skq = tid & 3;
    const __nv_bfloat16* pAh = Ah + offA + (long long)(bm + srow) * K + skq * 8;
    const __nv_bfloat16* pAl = Al + offA + (long long)(bm + srow) * K + skq * 8;
    const __nv_bfloat16* pBh = Bh + offB + (long long)(bn + srow) * K + skq * 8;
    const __nv_bfloat16* pBl = Bl + offB + (long long)(bn + srow) * K + skq * 8;
    const long long rstep = 64LL * K;
    const uint32_t sdst = srow * RSB + skq * 16;

    auto stage_load = [&](int t) {
        const int k0 = t * BK;
        const uint32_t d = sb + (t & 1) * STAGE + sdst;
        cpa16(d + OFF_AHI,            pAh + k0);
        cpa16(d + OFF_AHI + 64 * RSB, pAh + k0 + rstep);
        cpa16(d + OFF_ALO,            pAl + k0);
        cpa16(d + OFF_ALO + 64 * RSB, pAl + k0 + rstep);
        cpa16(d + OFF_BHI,            pBh + k0);
        cpa16(d + OFF_BHI + 64 * RSB, pBh + k0 + rstep);
        cpa16(d + OFF_BLO,            pBl + k0);
        cpa16(d + OFF_BLO + 64 * RSB, pBl + k0 + rstep);
        cp_commit();
    };

    float acc[4][4][4];
#pragma unroll
    for (int i = 0; i < 4; ++i)
#pragma unroll
        for (int j = 0; j < 4; ++j)
#pragma unroll
            for (int r = 0; r < 4; ++r) acc[i][j][r] = 0.f;

    const int wm = (warp & 1) * 64, wn = (warp >> 1) * 32;
    const int aRow   = wm + (lane & 7) + ((lane >> 3) & 1) * 8;
    const int aChunk = (lane >> 4) * 16;
    const int bRow   = wn + (lane & 7) + (lane >> 4) * 8;
    const int bChunk = ((lane >> 3) & 1) * 16;

    stage_load(0);
    const int nk = K / BK;

    for (int t = 0; t < nk; ++t) {
        cp_wait<0>();
        __syncthreads();                       // single barrier per k-tile
        if (t + 1 < nk) stage_load(t + 1);

        const uint32_t ss = sb + (t & 1) * STAGE;
#pragma unroll
        for (int kk = 0; kk < 2; ++kk) {
            const uint32_t kb = kk * 32;
            uint32_t ah[4][4], bh2[4][2], bl2[4][2];
#pragma unroll
            for (int i = 0; i < 4; ++i)
                ldsm4(ah[i][0], ah[i][1], ah[i][2], ah[i][3],
                      ss + OFF_AHI + (aRow + i * 16) * RSB + kb + aChunk);
#pragma unroll
            for (int jj = 0; jj < 2; ++jj) {
                uint32_t r0, r1, r2, r3;
                ldsm4(r0, r1, r2, r3, ss + OFF_BHI + (bRow + jj * 16) * RSB + kb + bChunk);
                bh2[2 * jj][0] = r0; bh2[2 * jj][1] = r1;
                bh2[2 * jj + 1][0] = r2; bh2[2 * jj + 1][1] = r3;
            }
#pragma unroll
            for (int i = 0; i < 4; ++i)
#pragma unroll
                for (int j = 0; j < 4; ++j) mma_bf16(acc[i][j], ah[i], bh2[j]);
#pragma unroll
            for (int jj = 0; jj < 2; ++jj) {
                uint32_t r0, r1, r2, r3;
                ldsm4(r0, r1, r2, r3, ss + OFF_BLO + (bRow + jj * 16) * RSB + kb + bChunk);
                bl2[2 * jj][0] = r0; bl2[2 * jj][1] = r1;
                bl2[2 * jj + 1][0] = r2; bl2[2 * jj + 1][1] = r3;
            }
#pragma unroll
            for (int i = 0; i < 4; ++i)
#pragma unroll
                for (int j = 0; j < 4; ++j) mma_bf16(acc[i][j], ah[i], bl2[j]);
#pragma unroll
            for (int i = 0; i < 4; ++i)
                ldsm4(ah[i][0], ah[i][1], ah[i][2], ah[i][3],
                      ss + OFF_ALO + (aRow + i * 16) * RSB + kb + aChunk);
#pragma unroll
            for (int i = 0; i < 4; ++i)
#pragma unroll
                for (int j = 0; j < 4; ++j) mma_bf16(acc[i][j], ah[i], bh2[j]);
        }
    }

    const int ar = lane >> 2, ac = lane & 3;
    const bool doT = (OM == 2) || (OM == 4 && zc < 2);

    if (doT) {
        __syncthreads();   // all warps done reading stage smem before reuse
        float* tb = reinterpret_cast<float*>(smem);
        const int TLD = 132;
#pragma unroll
        for (int i = 0; i < 4; ++i) {
            int m0 = wm + i * 16 + ar;
#pragma unroll
            for (int j = 0; j < 4; ++j) {
                int n0 = wn + j * 8 + ac * 2;
                float v0 = acc[i][j][0], v1 = acc[i][j][1];
                float v2 = acc[i][j][2], v3 = acc[i][j][3];
                if (RO) {
                    v0 = fmaxf(v0, 0.f); v1 = fmaxf(v1, 0.f);
                    v2 = fmaxf(v2, 0.f); v3 = fmaxf(v3, 0.f);
                }
                tb[n0 * TLD + m0]           = v0;
                tb[(n0 + 1) * TLD + m0]     = v1;
                tb[n0 * TLD + m0 + 8]       = v2;
                tb[(n0 + 1) * TLD + m0 + 8] = v3;
            }
        }
        __syncthreads();
        const int n = tid >> 1, mh = (tid & 1) * 64;
        const long long ro = cOff + (long long)(bn + n) * ldt + bm + mh;
#pragma unroll
        for (int mm = 0; mm < 64; mm += 8) {
            float4 a = *reinterpret_cast<float4*>(&tb[n * TLD + mh + mm]);
            float4 b = *reinterpret_cast<float4*>(&tb[n * TLD + mh + mm + 4]);
            __nv_bfloat162 h0 = __floats2bfloat162_rn(a.x, a.y), h1 = __floats2bfloat162_rn(a.z, a.w);
            __nv_bfloat162 h2 = __floats2bfloat162_rn(b.x, b.y), h3 = __floats2bfloat162_rn(b.z, b.w);
            __nv_bfloat162 l0 = __floats2bfloat162_rn(a.x - __bfloat162float(h0.x), a.y - __bfloat162float(h0.y));
            __nv_bfloat162 l1 = __floats2bfloat162_rn(a.z - __bfloat162float(h1.x), a.w - __bfloat162float(h1.y));
            __nv_bfloat162 l2 = __floats2bfloat162_rn(b.x - __bfloat162float(h2.x), b.y - __bfloat162float(h2.y));
            __nv_bfloat162 l3 = __floats2bfloat162_rn(b.z - __bfloat162float(h3.x), b.w - __bfloat162float(h3.y));
            *reinterpret_cast<uint4*>(Coh + ro + mm) = make_uint4(pack2(h0), pack2(h1), pack2(h2), pack2(h3));
            *reinterpret_cast<uint4*>(Col + ro + mm) = make_uint4(pack2(l0), pack2(l1), pack2(l2), pack2(l3));
        }
        return;
    }

    if (OM == 4) {
        // v branch: layout-split store via smuggled pointers, offset zh*sC1 only
        __nv_bfloat16* voh = (__nv_bfloat16*)Cf;
        __nv_bfloat16* vol = (__nv_bfloat16*)Res;
        const long long vOff = (long long)zh * sC1;
#pragma unroll
        for (int i = 0; i < 4; ++i) {
            int m0 = bm + wm + i * 16 + ar;
#pragma unroll
            for (int j = 0; j < 4; ++j) {
                int n0 = bn + wn + j * 8 + ac * 2;
                long long o0 = vOff + (long long)m0 * N + n0;
                long long o1 = o0 + 8LL * N;
                float v0 = acc[i][j][0], v1 = acc[i][j][1];
                float v2 = acc[i][j][2], v3 = acc[i][j][3];
                __nv_bfloat162 h0 = __floats2bfloat162_rn(v0, v1);
                __nv_bfloat162 l0 = __floats2bfloat162_rn(v0 - __bfloat162float(h0.x),
                                                          v1 - __bfloat162float(h0.y));
                __nv_bfloat162 h1 = __floats2bfloat162_rn(v2, v3);
                __nv_bfloat162 l1 = __floats2bfloat162_rn(v2 - __bfloat162float(h1.x),
                                                          v3 - __bfloat162float(h1.y));
                reinterpret_cast<__nv_bfloat162*>(voh)[o0 >> 1] = h0;
                reinterpret_cast<__nv_bfloat162*>(vol)[o0 >> 1] = l0;
                reinterpret_cast<__nv_bfloat162*>(voh)[o1 >> 1] = h1;
                reinterpret_cast<__nv_bfloat162*>(vol)[o1 >> 1] = l1;
            }
        }
        return;
    }

#pragma unroll
    for (int i = 0; i < 4; ++i) {
        int m0 = bm + wm + i * 16 + ar;
#pragma unroll
        for (int j = 0; j < 4; ++j) {
            int n0 = bn + wn + j * 8 + ac * 2;
            long long o0 = cOff + (long long)m0 * N + n0;
            long long o1 = o0 + 8LL * N;
            float v0 = acc[i][j][0], v1 = acc[i][j][1];
            float v2 = acc[i][j][2], v3 = acc[i][j][3];
            if (RES) {  // residual indexed WITHOUT z offset (shared across z)
                long long r0i = o0 - cOff, r1i = o1 - cOff;
                v0 += Res[r0i]; v1 += Res[r0i + 1];
                v2 += Res[r1i]; v3 += Res[r1i + 1];
            }
            if (RO) {
                v0 = fmaxf(v0, 0.f); v1 = fmaxf(v1, 0.f);
                v2 = fmaxf(v2, 0.f); v3 = fmaxf(v3, 0.f);
            }
            if (OM == 0) {
                *reinterpret_cast<float2*>(Cf + o0) = make_float2(v0, v1);
                *reinterpret_cast<float2*>(Cf + o1) = make_float2(v2, v3);
            } else {
                __nv_bfloat162 h0 = __floats2bfloat162_rn(v0, v1);
                __nv_bfloat162 l0 = __floats2bfloat162_rn(v0 - __bfloat162float(h0.x),
                                                          v1 - __bfloat162float(h0.y));
                __nv_bfloat162 h1 = __floats2bfloat162_rn(v2, v3);
                __nv_bfloat162 l1 = __floats2bfloat162_rn(v2 - __bfloat162float(h1.x),
                                                          v3 - __bfloat162float(h1.y));
                reinterpret_cast<__nv_bfloat162*>(Coh)[o0 >> 1] = h0;
                reinterpret_cast<__nv_bfloat162*>(Col)[o0 >> 1] = l0;
                reinterpret_cast<__nv_bfloat162*>(Coh)[o1 >> 1] = h1;
                reinterpret_cast<__nv_bfloat162*>(Col)[o1 >> 1] = l1;
            }
        }
    }
}

// ---------------- split (same layout): fp32 -> bf16 hi/lo ----------------
__global__ void split_rm(const float* __restrict__ in,
                         __nv_bfloat16* __restrict__ oh, __nv_bfloat16* __restrict__ ol,
                         long long n)
{
    long long i = ((long long)blockIdx.x * blockDim.x + threadIdx.x) * 4;
    if (i >= n) return;
    float4 v = *reinterpret_cast<const float4*>(in + i);
    __nv_bfloat162 h0 = __floats2bfloat162_rn(v.x, v.y);
    __nv_bfloat162 h1 = __floats2bfloat162_rn(v.z, v.w);
    __nv_bfloat162 l0 = __floats2bfloat162_rn(v.x - __bfloat162float(h0.x), v.y - __bfloat162float(h0.y));
    __nv_bfloat162 l1 = __floats2bfloat162_rn(v.z - __bfloat162float(h1.x), v.w - __bfloat162float(h1.y));
    *reinterpret_cast<uint2*>(oh + i) = make_uint2(pack2(h0), pack2(h1));
    *reinterpret_cast<uint2*>(ol + i) = make_uint2(pack2(l0), pack2(l1));
}

// ---------------- transpose + split: fp32 (R,C) -> bf16 hi/lo (C,R) ----------------
template<bool RELU>
__global__ void transpose_split(const float* __restrict__ in,
                                __nv_bfloat16* __restrict__ oh, __nv_bfloat16* __restrict__ ol,
                                int R, int C)
{
    __shared__ float tile[32][33];
    const int tx = threadIdx.x, ty = threadIdx.y;
    const int r0 = blockIdx.y * 32, c0 = blockIdx.x * 32;
#pragma unroll
    for (int i = 0; i < 4; ++i)
        tile[ty + 8 * i][tx] = in[(long long)(r0 + ty + 8 * i) * C + c0 + tx];
    __syncthreads();
#pragma unroll
    for (int i = 0; i < 4; ++i) {
        int c = c0 + ty + 8 * i, r = r0 + tx;
        float v = tile[tx][ty + 8 * i];
        if (RELU) v = fmaxf(v, 0.f);
        __nv_bfloat16 h = __float2bfloat16(v);
        __nv_bfloat16 l = __float2bfloat16(v - __bfloat162float(h));
        oh[(long long)c * R + r] = h;
        ol[(long long)c * R + r] = l;
    }
}

// ---------------- fused residual add + layernorm + transposed-split emit ----------------
// y = LN(a+b). WX: also write y fp32. TRELU: transpose-split of relu(y) else y.
template<bool TRELU, bool WX>
__global__ void add_ln_t(const float* __restrict__ a, const float* __restrict__ b,
                         const float* __restrict__ w, const float* __restrict__ bias,
                         float* __restrict__ out,
                         __nv_bfloat16* __restrict__ th, __nv_bfloat16* __restrict__ tl)
{
    const int row = blockIdx.x;
    const int tid = threadIdx.x;
    const long long base = (long long)row * SEQ_;
    float v[4];
    float s = 0.f, ss = 0.f;
#pragma unroll
    for (int i = 0; i < 4; ++i) {
        int col = tid + i * 256;
        float t = a[base + col] + b[base + col];
        v[i] = t; s += t; ss += t * t;
    }
#pragma unroll
    for (int o = 16; o > 0; o >>= 1) {
        s  += __shfl_xor_sync(0xffffffffu, s,  o);
        ss += __shfl_xor_sync(0xffffffffu, ss, o);
    }
    __shared__ float rs[8], rss[8];
    if ((tid & 31) == 0) { rs[tid >> 5] = s; rss[tid >> 5] = ss; }
    __syncthreads();
    s = 0.f; ss = 0.f;
#pragma unroll
    for (int i = 0; i < 8; ++i) { s += rs[i]; ss += rss[i]; }
    const float mu  = s  * (1.0f / SEQ_);
    const float var = ss * (1.0f / SEQ_) - mu * mu;
    const float inv = rsqrtf(var + 1e-6f);
#pragma unroll
    for (int i = 0; i < 4; ++i) {
        int col = tid + i * 256;
        float y = (v[i] - mu) * inv * w[col] + bias[col];
        if (WX) out[base + col] = y;
        float yt = TRELU ? fmaxf(y, 0.f) : y;
        __nv_bfloat16 h = __float2bfloat16(yt);
        __nv_bfloat16 l = __float2bfloat16(yt - __bfloat162float(h));
        th[(long long)col * IN_ + row] = h;
        tl[(long long)col * IN_ + row] = l;
    }
}

// ---------------- host orchestration ----------------
struct WSet {
    __nv_bfloat16 *wqh, *wql, *W1h, *W1l, *W2h, *W2l, *c1h, *c1l, *c2h, *c2l;
};
struct Bufs {
    float *mout, *x2;
    __nv_bfloat16 *xTh, *xTl, *qh, *ql, *hbh, *hbl, *qkTh, *qkTl,
                  *vh, *vl, *bTh, *bTl, *aTh, *aTl, *zTh, *zTl;
};

static inline unsigned nb4(long long n) { return (unsigned)((n / 4 + 255) / 256); }
static inline void wait_ev(cudaEvent_t ev) { cudaStreamWaitEvent((cudaStream_t)0, ev, 0); }

static cudaStream_t s2;
static cudaEvent_t evS, evA, evB, evC, evD, evE, evF;

static void launch_mha(const WSet& W, const Bufs& B)
{
    const long long IS = (long long)IN_ * SEQ_;
    const long long IM = (long long)IN_ * MID_;
    const long long SM = (long long)SEQ_ * MID_;
    const long long SI = (long long)SEQ_ * IN_;

    // 1. qkvS = split(relu(wqkv[c] @ x))           M=IN N=SEQ K=IN, z=3
    gemm_hmma<true,false,1><<<dim3(SEQ_/BN, IN_/BM, 3), 256, GSMEM>>>(
        W.wqh, W.wql, B.xTh, B.xTl, nullptr, B.qh, B.ql, nullptr,
        IN_, SEQ_, IN_, 0, (long long)IN_*IN_, 0, 0, 0, IS, 0, 1);

    // 2. hbS = split(relu(qkvS[c] @ W1[h,c]^T))    M=IN N=MID K=SEQ, z=24
    gemm_hmma<true,false,1><<<dim3(MID_/BN, IN_/BM, H_*3), 256, GSMEM>>>(
        B.qh, B.ql, W.W1h, W.W1l, nullptr, B.hbh, B.hbl, nullptr,
        IN_, MID_, SEQ_, 0, 0, IS,
        3LL*MID_*SEQ_, (long long)MID_*SEQ_, 3*IM, IM, 3);

    // 3. merged q/k/v projection (OM=4)            M=IN N=SEQ K=MID, z=24
    //    zc<2 -> qkT transposed-split (off zh*SI + zc*H*SI); zc==2 -> vS split (off zh*SI)
    gemm_hmma<false,false,4><<<dim3(SEQ_/BN, IN_/BM, H_*3), 256, GSMEM>>>(
        B.hbh, B.hbl, W.W2h, W.W2l,
        (float*)B.vh, B.qkTh, B.qkTl, (const float*)B.vl,
        IN_, SEQ_, MID_, IN_,
        3*IM, IM, 3*SM, SM, SI, (long long)H_*SI, 3);

    // 4. bTS = split(qT @ kT^T)                    M=SEQ N=SEQ K=IN, z=8
    gemm_hmma<false,false,1><<<dim3(SEQ_/BN, SEQ_/BM, H_), 256, GSMEM>>>(
        B.qkTh, B.qkTl, B.qkTh + (long long)H_*SI, B.qkTl + (long long)H_*SI,
        nullptr, B.bTh, B.bTl, nullptr,
        SEQ_, SEQ_, IN_, 0, SI, 0, SI, 0, (long long)SEQ_*SEQ_, 0, 1);

    // 5. aT = splitT(relu(vS @ bTS^T))             M=IN N=SEQ K=SEQ, z=8, OM=2
    gemm_hmma<true,false,2><<<dim3(SEQ_/BN, IN_/BM, H_), 256, GSMEM>>>(
        B.vh, B.vl, B.bTh, B.bTl, nullptr, B.aTh, B.aTl, nullptr,
        IN_, SEQ_, SEQ_, H_*IN_, IS, 0, (long long)SEQ_*SEQ_, 0, IN_, 0, 1);

    // 6. zT = splitT(relu(cW1 @ relu(cat)))        M=MID N=SEQ K=4096, OM=2
    gemm_hmma<true,false,2><<<dim3(SEQ_/BN, MID_/BM, 1), 256, GSMEM>>>(
        W.c1h, W.c1l, B.aTh, B.aTl, nullptr, B.zTh, B.zTl, nullptr,
        MID_, SEQ_, H_*IN_, MID_, 0,0, 0,0, 0,0, 1);

    // 7. mout = cW2 @ relu(z1) (fp32)              M=IN N=SEQ K=MID
    gemm_hmma<false,false,0><<<dim3(SEQ_/BN, IN_/BM, 1), 256, GSMEM>>>(
        W.c2h, W.c2l, B.zTh, B.zTl, B.mout,
        (__nv_bfloat16*)nullptr, (__nv_bfloat16*)nullptr, nullptr,
        IN_, SEQ_, MID_, 0, 0,0, 0,0, 0,0, 1);
}

extern "C" void kernel_launch(void* const* d_in, const int* in_sizes, int n_in,
                              void* d_out, int out_size)
{
    (void)in_sizes; (void)n_in; (void)out_size;

    const float* inp     = (const float*)d_in[0];
    const float* w_qkv_1 = (const float*)d_in[1];
    const float* w_qkv_2 = (const float*)d_in[2];
    const float* mh1_W1  = (const float*)d_in[3];
    const float* mh1_W2  = (const float*)d_in[4];
    const float* mh2_W1  = (const float*)d_in[5];
    const float* mh2_W2  = (const float*)d_in[6];
    const float* c1_W1   = (const float*)d_in[7];
    const float* c1_W2   = (const float*)d_in[8];
    const float* c2_W1   = (const float*)d_in[9];
    const float* c2_W2   = (const float*)d_in[10];
    const float* l1_W1   = (const float*)d_in[11];
    const float* l1_W2   = (const float*)d_in[12];
    const float* l2_W1   = (const float*)d_in[13];
    const float* l2_W2   = (const float*)d_in[14];
    const float* norm_w  = (const float*)d_in[15];
    const float* norm_b  = (const float*)d_in[16];
    float* out = (float*)d_out;

    static bool inited = false;
    if (!inited) {
        cudaStreamCreateWithFlags(&s2, cudaStreamNonBlocking);
        cudaEvent_t* evs[] = {&evS,&evA,&evB,&evC,&evD,&evE,&evF};
        for (auto e : evs) cudaEventCreateWithFlags(e, cudaEventDisableTiming);
        cudaFuncSetAttribute(gemm_hmma<true,false,1>,  cudaFuncAttributeMaxDynamicSharedMemorySize, GSMEM);
        cudaFuncSetAttribute(gemm_hmma<false,false,1>, cudaFuncAttributeMaxDynamicSharedMemorySize, GSMEM);
        cudaFuncSetAttribute(gemm_hmma<false,false,4>, cudaFuncAttributeMaxDynamicSharedMemorySize, GSMEM);
        cudaFuncSetAttribute(gemm_hmma<true,false,2>,  cudaFuncAttributeMaxDynamicSharedMemorySize, GSMEM);
        cudaFuncSetAttribute(gemm_hmma<false,false,0>, cudaFuncAttributeMaxDynamicSharedMemorySize, GSMEM);
        cudaFuncSetAttribute(gemm_hmma<false,true,0>,  cudaFuncAttributeMaxDynamicSharedMemorySize, GSMEM);
        inited = true;
    }

    Bufs B;
    cudaGetSymbolAddress((void**)&B.mout, g_mout);
    cudaGetSymbolAddress((void**)&B.x2,   g_x2);
    cudaGetSymbolAddress((void**)&B.xTh,  g_xT_h);   cudaGetSymbolAddress((void**)&B.xTl,  g_xT_l);
    cudaGetSymbolAddress((void**)&B.qh,   g_qkvS_h); cudaGetSymbolAddress((void**)&B.ql,   g_qkvS_l);
    cudaGetSymbolAddress((void**)&B.hbh,  g_hbS_h);  cudaGetSymbolAddress((void**)&B.hbl,  g_hbS_l);
    cudaGetSymbolAddress((void**)&B.qkTh, g_qkT_h);  cudaGetSymbolAddress((void**)&B.qkTl, g_qkT_l);
    cudaGetSymbolAddress((void**)&B.vh,   g_vS_h);   cudaGetSymbolAddress((void**)&B.vl,   g_vS_l);
    cudaGetSymbolAddress((void**)&B.bTh,  g_bTS_h);  cudaGetSymbolAddress((void**)&B.bTl,  g_bTS_l);
    cudaGetSymbolAddress((void**)&B.aTh,  g_aT_h);   cudaGetSymbolAddress((void**)&B.aTl,  g_aT_l);
    cudaGetSymbolAddress((void**)&B.zTh,  g_zT_h);   cudaGetSymbolAddress((void**)&B.zTl,  g_zT_l);

    WSet W1s, W2s;
    cudaGetSymbolAddress((void**)&W1s.wqh, g_wq1_h); cudaGetSymbolAddress((void**)&W1s.wql, g_wq1_l);
    cudaGetSymbolAddress((void**)&W1s.W1h, g_W1a_h); cudaGetSymbolAddress((void**)&W1s.W1l, g_W1a_l);
    cudaGetSymbolAddress((void**)&W1s.W2h, g_W2a_h); cudaGetSymbolAddress((void**)&W1s.W2l, g_W2a_l);
    cudaGetSymbolAddress((void**)&W1s.c1h, g_c1a_h); cudaGetSymbolAddress((void**)&W1s.c1l, g_c1a_l);
    cudaGetSymbolAddress((void**)&W1s.c2h, g_c2a_h); cudaGetSymbolAddress((void**)&W1s.c2l, g_c2a_l);
    cudaGetSymbolAddress((void**)&W2s.wqh, g_wq2_h); cudaGetSymbolAddress((void**)&W2s.wql, g_wq2_l);
    cudaGetSymbolAddress((void**)&W2s.W1h, g_W1b_h); cudaGetSymbolAddress((void**)&W2s.W1l, g_W1b_l);
    cudaGetSymbolAddress((void**)&W2s.W2h, g_W2b_h); cudaGetSymbolAddress((void**)&W2s.W2l, g_W2b_l);
    cudaGetSymbolAddress((void**)&W2s.c1h, g_c1b_h); cudaGetSymbolAddress((void**)&W2s.c1l, g_c1b_l);
    cudaGetSymbolAddress((void**)&W2s.c2h, g_c2b_h); cudaGetSymbolAddress((void**)&W2s.c2l, g_c2b_l);
    __nv_bfloat16 *WaSh, *WaSl, *WbSh, *WbSl;
    cudaGetSymbolAddress((void**)&WaSh, g_WaS_h); cudaGetSymbolAddress((void**)&WaSl, g_WaS_l);
    cudaGetSymbolAddress((void**)&WbSh, g_WbS_h); cudaGetSymbolAddress((void**)&WbSl, g_WbS_l);

    const long long nWQ = 3LL*IN_*IN_, nW1 = 24LL*MID_*SEQ_, nW2 = 24LL*SEQ_*MID_;
    const long long nC1 = (long long)MID_*H_*IN_, nC2 = (long long)IN_*MID_;
    const long long nWa = (long long)MID_*IN_, nWb = (long long)IN_*MID_;
    const long long IS = (long long)IN_ * SEQ_;

    // ---- fork side stream: all weight splits overlap the GEMM chain ----
    cudaEventRecord(evS, 0);
    cudaStreamWaitEvent(s2, evS, 0);
    split_rm<<<nb4(nWQ), 256, 0, s2>>>(w_qkv_1, W1s.wqh, W1s.wql, nWQ);
    cudaEventRecord(evA, s2);
    split_rm<<<nb4(nW1), 256, 0, s2>>>(mh1_W1, W1s.W1h, W1s.W1l, nW1);
    cudaEventRecord(evB, s2);
    split_rm<<<nb4(nW2), 256, 0, s2>>>(mh1_W2, W1s.W2h, W1s.W2l, nW2);
    cudaEventRecord(evC, s2);
    split_rm<<<nb4(nC1), 256, 0, s2>>>(c1_W1, W1s.c1h, W1s.c1l, nC1);
    split_rm<<<nb4(nC2), 256, 0, s2>>>(c1_W2, W1s.c2h, W1s.c2l, nC2);
    cudaEventRecord(evD, s2);
    split_rm<<<nb4(nWQ), 256, 0, s2>>>(w_qkv_2, W2s.wqh, W2s.wql, nWQ);
    split_rm<<<nb4(nW1), 256, 0, s2>>>(mh2_W1, W2s.W1h, W2s.W1l, nW1);
    split_rm<<<nb4(nW2), 256, 0, s2>>>(mh2_W2, W2s.W2h, W2s.W2l, nW2);
    split_rm<<<nb4(nC1), 256, 0, s2>>>(c2_W1, W2s.c1h, W2s.c1l, nC1);
    split_rm<<<nb4(nC2), 256, 0, s2>>>(c2_W2, W2s.c2h, W2s.c2l, nC2);
    cudaEventRecord(evE, s2);
    split_rm<<<nb4(nWa), 256, 0, s2>>>(l1_W1, WaSh,        WaSl,        nWa);
    split_rm<<<nb4(nWa), 256, 0, s2>>>(l2_W1, WaSh + nWa,  WaSl + nWa,  nWa);
    split_rm<<<nb4(nWb), 256, 0, s2>>>(l1_W2, WbSh,        WbSl,        nWb);
    split_rm<<<nb4(nWb), 256, 0, s2>>>(l2_W2, WbSh + nWb,  WbSl + nWb,  nWb);
    cudaEventRecord(evF, s2);

    // ---- Block 1: x1 = LN(inp + MHA1(inp)) ---- (fine-grained weight waits)
    transpose_split<false><<<dim3(SEQ_/32, IN_/32), dim3(32,8)>>>(inp, B.xTh, B.xTl, IN_, SEQ_);
    wait_ev(evA);
    {
        const long long IM = (long long)IN_*MID_, SM = (long long)SEQ_*MID_,
                        SI = (long long)SEQ_*IN_;
        gemm_hmma<true,false,1><<<dim3(SEQ_/BN, IN_/BM, 3), 256, GSMEM>>>(
            W1s.wqh, W1s.wql, B.xTh, B.xTl, nullptr, B.qh, B.ql, nullptr,
            IN_, SEQ_, IN_, 0, (long long)IN_*IN_, 0, 0, 0, IS, 0, 1);
        wait_ev(evB);
        gemm_hmma<true,false,1><<<dim3(MID_/BN, IN_/BM, H_*3), 256, GSMEM>>>(
            B.qh, B.ql, W1s.W1h, W1s.W1l, nullptr, B.hbh, B.hbl, nullptr,
            IN_, MID_, SEQ_, 0, 0, IS,
            3LL*MID_*SEQ_, (long long)MID_*SEQ_, 3*IM, IM, 3);
        wait_ev(evC);
        gemm_hmma<false,false,4><<<dim3(SEQ_/BN, IN_/BM, H_*3), 256, GSMEM>>>(
            B.hbh, B.hbl, W1s.W2h, W1s.W2l,
            (float*)B.vh, B.qkTh, B.qkTl, (const float*)B.vl,
            IN_, SEQ_, MID_, IN_,
            3*IM, IM, 3*SM, SM, SI, (long long)H_*SI, 3);
        gemm_hmma<false,false,1><<<dim3(SEQ_/BN, SEQ_/BM, H_), 256, GSMEM>>>(
            B.qkTh, B.qkTl, B.qkTh + (long long)H_*SI, B.qkTl + (long long)H_*SI,
            nullptr, B.bTh, B.bTl, nullptr,
            SEQ_, SEQ_, IN_, 0, SI, 0, SI, 0, (long long)SEQ_*SEQ_, 0, 1);
        gemm_hmma<true,false,2><<<dim3(SEQ_/BN, IN_/BM, H_), 256, GSMEM>>>(
            B.vh, B.vl, B.bTh, B.bTl, nullptr, B.aTh, B.aTl, nullptr,
            IN_, SEQ_, SEQ_, H_*IN_, IS, 0, (long long)SEQ_*SEQ_, 0, IN_, 0, 1);
        wait_ev(evD);
        gemm_hmma<true,false,2><<<dim3(SEQ_/BN, MID_/BM, 1), 256, GSMEM>>>(
            W1s.c1h, W1s.c1l, B.aTh, B.aTl, nullptr, B.zTh, B.zTl, nullptr,
            MID_, SEQ_, H_*IN_, MID_, 0,0, 0,0, 0,0, 1);
        gemm_hmma<false,false,0><<<dim3(SEQ_/BN, IN_/BM, 1), 256, GSMEM>>>(
            W1s.c2h, W1s.c2l, B.zTh, B.zTl, B.mout,
            (__nv_bfloat16*)nullptr, (__nv_bfloat16*)nullptr, nullptr,
            IN_, SEQ_, MID_, 0, 0,0, 0,0, 0,0, 1);
    }
    // x1 fp32 never needed (block-2 residual is inp) -> emit only x1^T split
    add_ln_t<false,false><<<IN_, 256>>>(inp, B.mout, norm_w, norm_b, nullptr, B.xTh, B.xTl);

    // ---- Block 2: x2 = LN(inp + MHA2(x1)) ----
    wait_ev(evE);
    launch_mha(W2s, B);
    // emit x2 fp32 (FFN residual) + relu(x2)^T split (FFN input)
    add_ln_t<true,true><<<IN_, 256>>>(inp, B.mout, norm_w, norm_b, B.x2, B.xTh, B.xTl);

    // ---- Two FFN heads as z=2 batched GEMMs ----
    wait_ev(evF);
    // zT[z] = splitT(relu(Wa[z] @ relu(x2)))       M=MID N=SEQ K=IN, z=2, OM=2
    gemm_hmma<true,false,2><<<dim3(SEQ_/BN, MID_/BM, 2), 256, GSMEM>>>(
        WaSh, WaSl, B.xTh, B.xTl, nullptr, B.zTh, B.zTl, nullptr,
        MID_, SEQ_, IN_, MID_,
        nWa, 0, 0, 0, (long long)SEQ_*MID_, 0, 1);
    // out[z] = Wb[z] @ relu(t[z]) + x2             M=IN N=SEQ K=MID, z=2, OM=0 RES
    gemm_hmma<false,true,0><<<dim3(SEQ_/BN, IN_/BM, 2), 256, GSMEM>>>(
        WbSh, WbSl, B.zTh, B.zTl, out,
        (__nv_bfloat16*)nullptr, (__nv_bfloat16*)nullptr, B.x2,
        IN_, SEQ_, MID_, 0,
        nWb, 0, (long long)SEQ_*MID_, 0, IS, 0, 1);
}

// round 16
// speedup vs baseline: 1.0241x; 1.0241x over previous
#include <cuda_runtime.h>
#include <cuda_bf16.h>
#include <cstdint>

// Problem dims
#define H_   8
#define IN_  512
#define SEQ_ 1024
#define MID_ 2048

// ---------------- HMMA GEMM tile config ----------------
constexpr int BM = 128, BN = 128, BK = 32;     // BK in bf16 k-elements per stage
constexpr int RSB = 80;                        // smem row stride bytes (64 data + 16 pad)
constexpr int OPB = 128 * RSB;                 // bytes per operand-half tile (10240)
constexpr int OFF_AHI = 0, OFF_ALO = OPB, OFF_BHI = 2 * OPB, OFF_BLO = 3 * OPB;
constexpr int STAGE = 4 * OPB;                 // 40960
constexpr int GSMEM = 2 * STAGE;               // 81920 bytes dynamic smem

// ---------------- scratch (device globals; no allocation allowed) ----------------
__device__ float g_mout[IN_ * SEQ_];
__device__ float g_x1  [IN_ * SEQ_];
__device__ float g_x2  [IN_ * SEQ_];
// activation split buffers
__device__ __nv_bfloat16 g_xT_h  [SEQ_ * IN_],           g_xT_l  [SEQ_ * IN_];
__device__ __nv_bfloat16 g_qkvS_h[3 * IN_ * SEQ_],       g_qkvS_l[3 * IN_ * SEQ_];
__device__ __nv_bfloat16 g_hbS_h [H_ * 3 * IN_ * MID_],  g_hbS_l [H_ * 3 * IN_ * MID_];
__device__ __nv_bfloat16 g_qkT_h [2 * H_ * SEQ_ * IN_],  g_qkT_l [2 * H_ * SEQ_ * IN_];
__device__ __nv_bfloat16 g_vS_h  [H_ * IN_ * SEQ_],      g_vS_l  [H_ * IN_ * SEQ_];
__device__ __nv_bfloat16 g_bTS_h [H_ * SEQ_ * SEQ_],     g_bTS_l [H_ * SEQ_ * SEQ_];
__device__ __nv_bfloat16 g_aT_h  [SEQ_ * H_ * IN_],      g_aT_l  [SEQ_ * H_ * IN_];
__device__ __nv_bfloat16 g_zT_h  [2 * SEQ_ * MID_],      g_zT_l  [2 * SEQ_ * MID_];
// per-block weight splits
__device__ __nv_bfloat16 g_wq1_h [3 * IN_ * IN_],        g_wq1_l [3 * IN_ * IN_];
__device__ __nv_bfloat16 g_wq2_h [3 * IN_ * IN_],        g_wq2_l [3 * IN_ * IN_];
__device__ __nv_bfloat16 g_W1a_h [H_ * 3 * MID_ * SEQ_], g_W1a_l [H_ * 3 * MID_ * SEQ_];
__device__ __nv_bfloat16 g_W1b_h [H_ * 3 * MID_ * SEQ_], g_W1b_l [H_ * 3 * MID_ * SEQ_];
__device__ __nv_bfloat16 g_W2a_h [H_ * 3 * SEQ_ * MID_], g_W2a_l [H_ * 3 * SEQ_ * MID_];
__device__ __nv_bfloat16 g_W2b_h [H_ * 3 * SEQ_ * MID_], g_W2b_l [H_ * 3 * SEQ_ * MID_];
__device__ __nv_bfloat16 g_c1a_h [MID_ * H_ * IN_],      g_c1a_l [MID_ * H_ * IN_];
__device__ __nv_bfloat16 g_c1b_h [MID_ * H_ * IN_],      g_c1b_l [MID_ * H_ * IN_];
__device__ __nv_bfloat16 g_c2a_h [IN_ * MID_],           g_c2a_l [IN_ * MID_];
__device__ __nv_bfloat16 g_c2b_h [IN_ * MID_],           g_c2b_l [IN_ * MID_];
// combined FFN weights (both heads contiguous -> z=2 batched GEMMs)
__device__ __nv_bfloat16 g_WaS_h [2 * MID_ * IN_],       g_WaS_l [2 * MID_ * IN_];
__device__ __nv_bfloat16 g_WbS_h [2 * IN_ * MID_],       g_WbS_l [2 * IN_ * MID_];

// ---------------- PTX helpers ----------------
__device__ __forceinline__ uint32_t smem_u32(const void* p) {
    uint32_t a;
    asm("{ .reg .u64 t; cvta.to.shared.u64 t, %1; cvt.u32.u64 %0, t; }" : "=r"(a) : "l"(p));
    return a;
}
__device__ __forceinline__ void cpa16(uint32_t d, const void* s) {
    asm volatile("cp.async.cg.shared.global [%0], [%1], 16;" :: "r"(d), "l"(s));
}
__device__ __forceinline__ void cp_commit() {
    asm volatile("cp.async.commit_group;" ::: "memory");
}
template<int N> __device__ __forceinline__ void cp_wait() {
    asm volatile("cp.async.wait_group %0;" :: "n"(N) : "memory");
}
__device__ __forceinline__ void ldsm4(uint32_t& r0, uint32_t& r1, uint32_t& r2, uint32_t& r3, uint32_t a) {
    asm volatile("ldmatrix.sync.aligned.m8n8.x4.shared.b16 {%0,%1,%2,%3}, [%4];"
                 : "=r"(r0), "=r"(r1), "=r"(r2), "=r"(r3) : "r"(a));
}
__device__ __forceinline__ void mma_bf16(float c[4], const uint32_t a[4], const uint32_t b[2]) {
    asm volatile(
        "mma.sync.aligned.m16n8k16.row.col.f32.bf16.bf16.f32 "
        "{%0,%1,%2,%3}, {%4,%5,%6,%7}, {%8,%9}, {%0,%1,%2,%3};\n"
        : "+f"(c[0]), "+f"(c[1]), "+f"(c[2]), "+f"(c[3])
        : "r"(a[0]), "r"(a[1]), "r"(a[2]), "r"(a[3]), "r"(b[0]), "r"(b[1]));
}
__device__ __forceinline__ uint32_t pack2(__nv_bfloat162 h) {
    return *reinterpret_cast<uint32_t*>(&h);
}

// ---------------- GEMM: C = act( A * B^T [+Res] ), operands pre-split bf16 hi/lo ----------------
// Single __syncthreads per k-tile:  wait -> sync -> stage(t+1) -> compute(t).
// OM=0: fp32 out (RO relu; RES residual indexed WITHOUT z offset — shared across z).
// OM=1: bf16 hi/lo split out, same layout.
// OM=2: bf16 hi/lo split out TRANSPOSED (row n, ld=ldt; RO relu).
template<bool RO, bool RES, int OM>
__global__ void __launch_bounds__(256, 2)
gemm_hmma(const __nv_bfloat16* __restrict__ Ah, const __nv_bfloat16* __restrict__ Al,
          const __nv_bfloat16* __restrict__ Bh, const __nv_bfloat16* __restrict__ Bl,
          float* __restrict__ Cf, __nv_bfloat16* __restrict__ Coh, __nv_bfloat16* __restrict__ Col,
          const float* __restrict__ Res,
          int M, int N, int K, int ldt,
          long long sA1, long long sA2, long long sB1, long long sB2,
          long long sC1, long long sC2, int zdiv)
{
    extern __shared__ char smem[];
    const int tid = threadIdx.x, lane = tid & 31, warp = tid >> 5;

    const int zz = blockIdx.z, zh = zz / zdiv, zc = zz - zh * zdiv;
    const long long offA = zh * sA1 + (long long)zc * sA2;
    const long long offB = zh * sB1 + (long long)zc * sB2;
    const long long cOff = zh * sC1 + (long long)zc * sC2;

    const int bm = blockIdx.y * BM, bn = blockIdx.x * BN;
    const uint32_t sb = smem_u32(smem);

    const int srow = tid >> 2, skq = tid & 3;
    const __nv_bfloat16* pAh = Ah + offA + (long long)(bm + srow) * K + skq * 8;
    const __nv_bfloat16* pAl = Al + offA + (long long)(bm + srow) * K + skq * 8;
    const __nv_bfloat16* pBh = Bh + offB + (long long)(bn + srow) * K + skq * 8;
    const __nv_bfloat16* pBl = Bl + offB + (long long)(bn + srow) * K + skq * 8;
    const long long rstep = 64LL * K;
    const uint32_t sdst = srow * RSB + skq * 16;

    auto stage_load = [&](int t) {
        const int k0 = t * BK;
        const uint32_t d = sb + (t & 1) * STAGE + sdst;
        cpa16(d + OFF_AHI,            pAh + k0);
        cpa16(d + OFF_AHI + 64 * RSB, pAh + k0 + rstep);
        cpa16(d + OFF_ALO,            pAl + k0);
        cpa16(d + OFF_ALO + 64 * RSB, pAl + k0 + rstep);
        cpa16(d + OFF_BHI,            pBh + k0);
        cpa16(d + OFF_BHI + 64 * RSB, pBh + k0 + rstep);
        cpa16(d + OFF_BLO,            pBl + k0);
        cpa16(d + OFF_BLO + 64 * RSB, pBl + k0 + rstep);
        cp_commit();
    };

    float acc[4][4][4];
#pragma unroll
    for (int i = 0; i < 4; ++i)
#pragma unroll
        for (int j = 0; j < 4; ++j)
#pragma unroll
            for (int r = 0; r < 4; ++r) acc[i][j][r] = 0.f;

    const int wm = (warp & 1) * 64, wn = (warp >> 1) * 32;
    const int aRow   = wm + (lane & 7) + ((lane >> 3) & 1) * 8;
    const int aChunk = (lane >> 4) * 16;
    const int bRow   = wn + (lane & 7) + (lane >> 4) * 8;
    const int bChunk = ((lane >> 3) & 1) * 16;

    stage_load(0);
    const int nk = K / BK;

    for (int t = 0; t < nk; ++t) {
        cp_wait<0>();
        __syncthreads();                       // single barrier per k-tile
        if (t + 1 < nk) stage_load(t + 1);

        const uint32_t ss = sb + (t & 1) * STAGE;
#pragma unroll
        for (int kk = 0; kk < 2; ++kk) {
            const uint32_t kb = kk * 32;
            uint32_t ah[4][4], bh2[4][2], bl2[4][2];
#pragma unroll
            for (int i = 0; i < 4; ++i)
                ldsm4(ah[i][0], ah[i][1], ah[i][2], ah[i][3],
                      ss + OFF_AHI + (aRow + i * 16) * RSB + kb + aChunk);
#pragma unroll
            for (int jj = 0; jj < 2; ++jj) {
                uint32_t r0, r1, r2, r3;
                ldsm4(r0, r1, r2, r3, ss + OFF_BHI + (bRow + jj * 16) * RSB + kb + bChunk);
                bh2[2 * jj][0] = r0; bh2[2 * jj][1] = r1;
                bh2[2 * jj + 1][0] = r2; bh2[2 * jj + 1][1] = r3;
            }
#pragma unroll
            for (int i = 0; i < 4; ++i)
#pragma unroll
                for (int j = 0; j < 4; ++j) mma_bf16(acc[i][j], ah[i], bh2[j]);
#pragma unroll
            for (int jj = 0; jj < 2; ++jj) {
                uint32_t r0, r1, r2, r3;
                ldsm4(r0, r1, r2, r3, ss + OFF_BLO + (bRow + jj * 16) * RSB + kb + bChunk);
                bl2[2 * jj][0] = r0; bl2[2 * jj][1] = r1;
                bl2[2 * jj + 1][0] = r2; bl2[2 * jj + 1][1] = r3;
            }
#pragma unroll
            for (int i = 0; i < 4; ++i)
#pragma unroll
                for (int j = 0; j < 4; ++j) mma_bf16(acc[i][j], ah[i], bl2[j]);
#pragma unroll
            for (int i = 0; i < 4; ++i)
                ldsm4(ah[i][0], ah[i][1], ah[i][2], ah[i][3],
                      ss + OFF_ALO + (aRow + i * 16) * RSB + kb + aChunk);
#pragma unroll
            for (int i = 0; i < 4; ++i)
#pragma unroll
                for (int j = 0; j < 4; ++j) mma_bf16(acc[i][j], ah[i], bh2[j]);
        }
    }

    const int ar = lane >> 2, ac = lane & 3;

    if (OM == 2) {
        __syncthreads();   // all warps done reading stage smem before reuse as transpose buffer
        float* tb = reinterpret_cast<float*>(smem);
        const int TLD = 132;
#pragma unroll
        for (int i = 0; i < 4; ++i) {
            int m0 = wm + i * 16 + ar;
#pragma unroll
            for (int j = 0; j < 4; ++j) {
                int n0 = wn + j * 8 + ac * 2;
                float v0 = acc[i][j][0], v1 = acc[i][j][1];
                float v2 = acc[i][j][2], v3 = acc[i][j][3];
                if (RO) {
                    v0 = fmaxf(v0, 0.f); v1 = fmaxf(v1, 0.f);
                    v2 = fmaxf(v2, 0.f); v3 = fmaxf(v3, 0.f);
                }
                tb[n0 * TLD + m0]           = v0;
                tb[(n0 + 1) * TLD + m0]     = v1;
                tb[n0 * TLD + m0 + 8]       = v2;
                tb[(n0 + 1) * TLD + m0 + 8] = v3;
            }
        }
        __syncthreads();
        const int n = tid >> 1, mh = (tid & 1) * 64;
        const long long ro = cOff + (long long)(bn + n) * ldt + bm + mh;
#pragma unroll
        for (int mm = 0; mm < 64; mm += 8) {
            float4 a = *reinterpret_cast<float4*>(&tb[n * TLD + mh + mm]);
            float4 b = *reinterpret_cast<float4*>(&tb[n * TLD + mh + mm + 4]);
            __nv_bfloat162 h0 = __floats2bfloat162_rn(a.x, a.y), h1 = __floats2bfloat162_rn(a.z, a.w);
            __nv_bfloat162 h2 = __floats2bfloat162_rn(b.x, b.y), h3 = __floats2bfloat162_rn(b.z, b.w);
            __nv_bfloat162 l0 = __floats2bfloat162_rn(a.x - __bfloat162float(h0.x), a.y - __bfloat162float(h0.y));
            __nv_bfloat162 l1 = __floats2bfloat162_rn(a.z - __bfloat162float(h1.x), a.w - __bfloat162float(h1.y));
            __nv_bfloat162 l2 = __floats2bfloat162_rn(b.x - __bfloat162float(h2.x), b.y - __bfloat162float(h2.y));
            __nv_bfloat162 l3 = __floats2bfloat162_rn(b.z - __bfloat162float(h3.x), b.w - __bfloat162float(h3.y));
            *reinterpret_cast<uint4*>(Coh + ro + mm) = make_uint4(pack2(h0), pack2(h1), pack2(h2), pack2(h3));
            *reinterpret_cast<uint4*>(Col + ro + mm) = make_uint4(pack2(l0), pack2(l1), pack2(l2), pack2(l3));
        }
        return;
    }

#pragma unroll
    for (int i = 0; i < 4; ++i) {
        int m0 = bm + wm + i * 16 + ar;
#pragma unroll
        for (int j = 0; j < 4; ++j) {
            int n0 = bn + wn + j * 8 + ac * 2;
            long long o0 = cOff + (long long)m0 * N + n0;
            long long o1 = o0 + 8LL * N;
            float v0 = acc[i][j][0], v1 = acc[i][j][1];
            float v2 = acc[i][j][2], v3 = acc[i][j][3];
            if (RES) {  // residual shared across z: index WITHOUT z offset
                long long r0i = o0 - cOff, r1i = o1 - cOff;
                v0 += Res[r0i]; v1 += Res[r0i + 1];
                v2 += Res[r1i]; v3 += Res[r1i + 1];
            }
            if (RO) {
                v0 = fmaxf(v0, 0.f); v1 = fmaxf(v1, 0.f);
                v2 = fmaxf(v2, 0.f); v3 = fmaxf(v3, 0.f);
            }
            if (OM == 0) {
                *reinterpret_cast<float2*>(Cf + o0) = make_float2(v0, v1);
                *reinterpret_cast<float2*>(Cf + o1) = make_float2(v2, v3);
            } else {
                __nv_bfloat162 h0 = __floats2bfloat162_rn(v0, v1);
                __nv_bfloat162 l0 = __floats2bfloat162_rn(v0 - __bfloat162float(h0.x),
                                                          v1 - __bfloat162float(h0.y));
                __nv_bfloat162 h1 = __floats2bfloat162_rn(v2, v3);
                __nv_bfloat162 l1 = __floats2bfloat162_rn(v2 - __bfloat162float(h1.x),
                                                          v3 - __bfloat162float(h1.y));
                reinterpret_cast<__nv_bfloat162*>(Coh)[o0 >> 1] = h0;
                reinterpret_cast<__nv_bfloat162*>(Col)[o0 >> 1] = l0;
                reinterpret_cast<__nv_bfloat162*>(Coh)[o1 >> 1] = h1;
                reinterpret_cast<__nv_bfloat162*>(Col)[o1 >> 1] = l1;
            }
        }
    }
}

// ---------------- split (same layout): fp32 -> bf16 hi/lo ----------------
__global__ void split_rm(const float* __restrict__ in,
                         __nv_bfloat16* __restrict__ oh, __nv_bfloat16* __restrict__ ol,
                         long long n)
{
    long long i = ((long long)blockIdx.x * blockDim.x + threadIdx.x) * 4;
    if (i >= n) return;
    float4 v = *reinterpret_cast<const float4*>(in + i);
    __nv_bfloat162 h0 = __floats2bfloat162_rn(v.x, v.y);
    __nv_bfloat162 h1 = __floats2bfloat162_rn(v.z, v.w);
    __nv_bfloat162 l0 = __floats2bfloat162_rn(v.x - __bfloat162float(h0.x), v.y - __bfloat162float(h0.y));
    __nv_bfloat162 l1 = __floats2bfloat162_rn(v.z - __bfloat162float(h1.x), v.w - __bfloat162float(h1.y));
    *reinterpret_cast<uint2*>(oh + i) = make_uint2(pack2(h0), pack2(h1));
    *reinterpret_cast<uint2*>(ol + i) = make_uint2(pack2(l0), pack2(l1));
}

// ---------------- transpose + split: fp32 (R,C) -> bf16 hi/lo (C,R) ----------------
template<bool RELU>
__global__ void transpose_split(const float* __restrict__ in,
                                __nv_bfloat16* __restrict__ oh, __nv_bfloat16* __restrict__ ol,
                                int R, int C)
{
    __shared__ float tile[32][33];
    const int tx = threadIdx.x, ty = threadIdx.y;
    const int r0 = blockIdx.y * 32, c0 = blockIdx.x * 32;
#pragma unroll
    for (int i = 0; i < 4; ++i)
        tile[ty + 8 * i][tx] = in[(long long)(r0 + ty + 8 * i) * C + c0 + tx];
    __syncthreads();
#pragma unroll
    for (int i = 0; i < 4; ++i) {
        int c = c0 + ty + 8 * i, r = r0 + tx;
        float v = tile[tx][ty + 8 * i];
        if (RELU) v = fmaxf(v, 0.f);
        __nv_bfloat16 h = __float2bfloat16(v);
        __nv_bfloat16 l = __float2bfloat16(v - __bfloat162float(h));
        oh[(long long)c * R + r] = h;
        ol[(long long)c * R + r] = l;
    }
}

// ---------------- fused residual add + layernorm over last axis (1024) ----------------
__global__ void add_ln_kernel(const float* __restrict__ a, const float* __restrict__ b,
                              const float* __restrict__ w, const float* __restrict__ bias,
                              float* __restrict__ out)
{
    const int row = blockIdx.x;
    const int tid = threadIdx.x;
    const long long base = (long long)row * SEQ_;
    float v[4];
    float s = 0.f, ss = 0.f;
#pragma unroll
    for (int i = 0; i < 4; ++i) {
        int col = tid + i * 256;
        float t = a[base + col] + b[base + col];
        v[i] = t; s += t; ss += t * t;
    }
#pragma unroll
    for (int o = 16; o > 0; o >>= 1) {
        s  += __shfl_xor_sync(0xffffffffu, s,  o);
        ss += __shfl_xor_sync(0xffffffffu, ss, o);
    }
    __shared__ float rs[8], rss[8];
    if ((tid & 31) == 0) { rs[tid >> 5] = s; rss[tid >> 5] = ss; }
    __syncthreads();
    s = 0.f; ss = 0.f;
#pragma unroll
    for (int i = 0; i < 8; ++i) { s += rs[i]; ss += rss[i]; }
    const float mu  = s  * (1.0f / SEQ_);
    const float var = ss * (1.0f / SEQ_) - mu * mu;
    const float inv = rsqrtf(var + 1e-6f);
#pragma unroll
    for (int i = 0; i < 4; ++i) {
        int col = tid + i * 256;
        out[base + col] = (v[i] - mu) * inv * w[col] + bias[col];
    }
}

// ---------------- host orchestration ----------------
struct WSet {
    __nv_bfloat16 *wqh, *wql, *W1h, *W1l, *W2h, *W2l, *c1h, *c1l, *c2h, *c2l;
};
struct Bufs {
    float *mout, *x1, *x2;
    __nv_bfloat16 *xTh, *xTl, *qh, *ql, *hbh, *hbl, *qkTh, *qkTl,
                  *vh, *vl, *bTh, *bTl, *aTh, *aTl, *zTh, *zTl;
};

static inline unsigned nb4(long long n) { return (unsigned)((n / 4 + 255) / 256); }
static inline void wait_ev(cudaEvent_t ev) { cudaStreamWaitEvent((cudaStream_t)0, ev, 0); }

static cudaStream_t s2;
static cudaEvent_t evS, evA, evB, evC, evD, evE, evF, evG, evH;

// One MHA block (weights ready). v-projection runs on s2 concurrently with qk path.
static void launch_mha(const WSet& W, const Bufs& B)
{
    const long long IS = (long long)IN_ * SEQ_;
    const long long IM = (long long)IN_ * MID_;
    const long long SM = (long long)SEQ_ * MID_;
    const long long SI = (long long)SEQ_ * IN_;

    gemm_hmma<true,false,1><<<dim3(SEQ_/BN, IN_/BM, 3), 256, GSMEM>>>(
        W.wqh, W.wql, B.xTh, B.xTl, nullptr, B.qh, B.ql, nullptr,
        IN_, SEQ_, IN_, 0, (long long)IN_*IN_, 0, 0, 0, IS, 0, 1);

    gemm_hmma<true,false,1><<<dim3(MID_/BN, IN_/BM, H_*3), 256, GSMEM>>>(
        B.qh, B.ql, W.W1h, W.W1l, nullptr, B.hbh, B.hbl, nullptr,
        IN_, MID_, SEQ_, 0, 0, IS,
        3LL*MID_*SEQ_, (long long)MID_*SEQ_, 3*IM, IM, 3);
    cudaEventRecord(evG, 0);

    // v projection on s2 (independent of qk path)
    cudaStreamWaitEvent(s2, evG, 0);
    gemm_hmma<false,false,1><<<dim3(SEQ_/BN, IN_/BM, H_), 256, GSMEM, s2>>>(
        B.hbh + 2*IM, B.hbl + 2*IM, W.W2h + 2*SM, W.W2l + 2*SM, nullptr, B.vh, B.vl, nullptr,
        IN_, SEQ_, MID_, 0, 3*IM, 0, 3*SM, 0, IS, 0, 1);
    cudaEventRecord(evH, s2);

    // qk path on main
    gemm_hmma<false,false,2><<<dim3(SEQ_/BN, IN_/BM, H_*2), 256, GSMEM>>>(
        B.hbh, B.hbl, W.W2h, W.W2l, nullptr, B.qkTh, B.qkTl, nullptr,
        IN_, SEQ_, MID_, IN_, 3*IM, IM, 3*SM, SM, SI, (long long)H_*SI, 2);

    gemm_hmma<false,false,1><<<dim3(SEQ_/BN, SEQ_/BM, H_), 256, GSMEM>>>(
        B.qkTh, B.qkTl, B.qkTh + (long long)H_*SI, B.qkTl + (long long)H_*SI,
        nullptr, B.bTh, B.bTl, nullptr,
        SEQ_, SEQ_, IN_, 0, SI, 0, SI, 0, (long long)SEQ_*SEQ_, 0, 1);

    wait_ev(evH);
    gemm_hmma<true,false,2><<<dim3(SEQ_/BN, IN_/BM, H_), 256, GSMEM>>>(
        B.vh, B.vl, B.bTh, B.bTl, nullptr, B.aTh, B.aTl, nullptr,
        IN_, SEQ_, SEQ_, H_*IN_, IS, 0, (long long)SEQ_*SEQ_, 0, IN_, 0, 1);

    gemm_hmma<true,false,2><<<dim3(SEQ_/BN, MID_/BM, 1), 256, GSMEM>>>(
        W.c1h, W.c1l, B.aTh, B.aTl, nullptr, B.zTh, B.zTl, nullptr,
        MID_, SEQ_, H_*IN_, MID_, 0,0, 0,0, 0,0, 1);

    gemm_hmma<false,false,0><<<dim3(SEQ_/BN, IN_/BM, 1), 256, GSMEM>>>(
        W.c2h, W.c2l, B.zTh, B.zTl, B.mout,
        (__nv_bfloat16*)nullptr, (__nv_bfloat16*)nullptr, nullptr,
        IN_, SEQ_, MID_, 0, 0,0, 0,0, 0,0, 1);
}

extern "C" void kernel_launch(void* const* d_in, const int* in_sizes, int n_in,
                              void* d_out, int out_size)
{
    (void)in_sizes; (void)n_in; (void)out_size;

    const float* inp     = (const float*)d_in[0];
    const float* w_qkv_1 = (const float*)d_in[1];
    const float* w_qkv_2 = (const float*)d_in[2];
    const float* mh1_W1  = (const float*)d_in[3];
    const float* mh1_W2  = (const float*)d_in[4];
    const float* mh2_W1  = (const float*)d_in[5];
    const float* mh2_W2  = (const float*)d_in[6];
    const float* c1_W1   = (const float*)d_in[7];
    const float* c1_W2   = (const float*)d_in[8];
    const float* c2_W1   = (const float*)d_in[9];
    const float* c2_W2   = (const float*)d_in[10];
    const float* l1_W1   = (const float*)d_in[11];
    const float* l1_W2   = (const float*)d_in[12];
    const float* l2_W1   = (const float*)d_in[13];
    const float* l2_W2   = (const float*)d_in[14];
    const float* norm_w  = (const float*)d_in[15];
    const float* norm_b  = (const float*)d_in[16];
    float* out = (float*)d_out;

    static bool inited = false;
    if (!inited) {
        cudaStreamCreateWithFlags(&s2, cudaStreamNonBlocking);
        cudaEvent_t* evs[] = {&evS,&evA,&evB,&evC,&evD,&evE,&evF,&evG,&evH};
        for (auto e : evs) cudaEventCreateWithFlags(e, cudaEventDisableTiming);
        cudaFuncSetAttribute(gemm_hmma<true,false,1>,  cudaFuncAttributeMaxDynamicSharedMemorySize, GSMEM);
        cudaFuncSetAttribute(gemm_hmma<false,false,1>, cudaFuncAttributeMaxDynamicSharedMemorySize, GSMEM);
        cudaFuncSetAttribute(gemm_hmma<false,false,2>, cudaFuncAttributeMaxDynamicSharedMemorySize, GSMEM);
        cudaFuncSetAttribute(gemm_hmma<true,false,2>,  cudaFuncAttributeMaxDynamicSharedMemorySize, GSMEM);
        cudaFuncSetAttribute(gemm_hmma<false,false,0>, cudaFuncAttributeMaxDynamicSharedMemorySize, GSMEM);
        cudaFuncSetAttribute(gemm_hmma<false,true,0>,  cudaFuncAttributeMaxDynamicSharedMemorySize, GSMEM);
        inited = true;
    }

    Bufs B;
    cudaGetSymbolAddress((void**)&B.mout, g_mout);
    cudaGetSymbolAddress((void**)&B.x1,   g_x1);
    cudaGetSymbolAddress((void**)&B.x2,   g_x2);
    cudaGetSymbolAddress((void**)&B.xTh,  g_xT_h);   cudaGetSymbolAddress((void**)&B.xTl,  g_xT_l);
    cudaGetSymbolAddress((void**)&B.qh,   g_qkvS_h); cudaGetSymbolAddress((void**)&B.ql,   g_qkvS_l);
    cudaGetSymbolAddress((void**)&B.hbh,  g_hbS_h);  cudaGetSymbolAddress((void**)&B.hbl,  g_hbS_l);
    cudaGetSymbolAddress((void**)&B.qkTh, g_qkT_h);  cudaGetSymbolAddress((void**)&B.qkTl, g_qkT_l);
    cudaGetSymbolAddress((void**)&B.vh,   g_vS_h);   cudaGetSymbolAddress((void**)&B.vl,   g_vS_l);
    cudaGetSymbolAddress((void**)&B.bTh,  g_bTS_h);  cudaGetSymbolAddress((void**)&B.bTl,  g_bTS_l);
    cudaGetSymbolAddress((void**)&B.aTh,  g_aT_h);   cudaGetSymbolAddress((void**)&B.aTl,  g_aT_l);
    cudaGetSymbolAddress((void**)&B.zTh,  g_zT_h);   cudaGetSymbolAddress((void**)&B.zTl,  g_zT_l);

    WSet W1s, W2s;
    cudaGetSymbolAddress((void**)&W1s.wqh, g_wq1_h); cudaGetSymbolAddress((void**)&W1s.wql, g_wq1_l);
    cudaGetSymbolAddress((void**)&W1s.W1h, g_W1a_h); cudaGetSymbolAddress((void**)&W1s.W1l, g_W1a_l);
    cudaGetSymbolAddress((void**)&W1s.W2h, g_W2a_h); cudaGetSymbolAddress((void**)&W1s.W2l, g_W2a_l);
    cudaGetSymbolAddress((void**)&W1s.c1h, g_c1a_h); cudaGetSymbolAddress((void**)&W1s.c1l, g_c1a_l);
    cudaGetSymbolAddress((void**)&W1s.c2h, g_c2a_h); cudaGetSymbolAddress((void**)&W1s.c2l, g_c2a_l);
    cudaGetSymbolAddress((void**)&W2s.wqh, g_wq2_h); cudaGetSymbolAddress((void**)&W2s.wql, g_wq2_l);
    cudaGetSymbolAddress((void**)&W2s.W1h, g_W1b_h); cudaGetSymbolAddress((void**)&W2s.W1l, g_W1b_l);
    cudaGetSymbolAddress((void**)&W2s.W2h, g_W2b_h); cudaGetSymbolAddress((void**)&W2s.W2l, g_W2b_l);
    cudaGetSymbolAddress((void**)&W2s.c1h, g_c1b_h); cudaGetSymbolAddress((void**)&W2s.c1l, g_c1b_l);
    cudaGetSymbolAddress((void**)&W2s.c2h, g_c2b_h); cudaGetSymbolAddress((void**)&W2s.c2l, g_c2b_l);
    __nv_bfloat16 *WaSh, *WaSl, *WbSh, *WbSl;
    cudaGetSymbolAddress((void**)&WaSh, g_WaS_h); cudaGetSymbolAddress((void**)&WaSl, g_WaS_l);
    cudaGetSymbolAddress((void**)&WbSh, g_WbS_h); cudaGetSymbolAddress((void**)&WbSl, g_WbS_l);

    const long long nWQ = 3LL*IN_*IN_, nW1 = 24LL*MID_*SEQ_, nW2 = 24LL*SEQ_*MID_;
    const long long nC1 = (long long)MID_*H_*IN_, nC2 = (long long)IN_*MID_;
    const long long nWa = (long long)MID_*IN_, nWb = (long long)IN_*MID_;
    const long long IS = (long long)IN_ * SEQ_;

    // ---- fork side stream: all weight splits overlap the GEMM chain ----
    cudaEventRecord(evS, 0);
    cudaStreamWaitEvent(s2, evS, 0);
    split_rm<<<nb4(nWQ), 256, 0, s2>>>(w_qkv_1, W1s.wqh, W1s.wql, nWQ);
    cudaEventRecord(evA, s2);
    split_rm<<<nb4(nW1), 256, 0, s2>>>(mh1_W1, W1s.W1h, W1s.W1l, nW1);
    cudaEventRecord(evB, s2);
    split_rm<<<nb4(nW2), 256, 0, s2>>>(mh1_W2, W1s.W2h, W1s.W2l, nW2);
    cudaEventRecord(evC, s2);
    split_rm<<<nb4(nC1), 256, 0, s2>>>(c1_W1, W1s.c1h, W1s.c1l, nC1);
    split_rm<<<nb4(nC2), 256, 0, s2>>>(c1_W2, W1s.c2h, W1s.c2l, nC2);
    cudaEventRecord(evD, s2);
    split_rm<<<nb4(nWQ), 256, 0, s2>>>(w_qkv_2, W2s.wqh, W2s.wql, nWQ);
    split_rm<<<nb4(nW1), 256, 0, s2>>>(mh2_W1, W2s.W1h, W2s.W1l, nW1);
    split_rm<<<nb4(nW2), 256, 0, s2>>>(mh2_W2, W2s.W2h, W2s.W2l, nW2);
    split_rm<<<nb4(nC1), 256, 0, s2>>>(c2_W1, W2s.c1h, W2s.c1l, nC1);
    split_rm<<<nb4(nC2), 256, 0, s2>>>(c2_W2, W2s.c2h, W2s.c2l, nC2);
    cudaEventRecord(evE, s2);
    split_rm<<<nb4(nWa), 256, 0, s2>>>(l1_W1, WaSh,       WaSl,       nWa);
    split_rm<<<nb4(nWa), 256, 0, s2>>>(l2_W1, WaSh + nWa, WaSl + nWa, nWa);
    split_rm<<<nb4(nWb), 256, 0, s2>>>(l1_W2, WbSh,       WbSl,       nWb);
    split_rm<<<nb4(nWb), 256, 0, s2>>>(l2_W2, WbSh + nWb, WbSl + nWb, nWb);
    cudaEventRecord(evF, s2);

    // ---- Block 1: x1 = LN(inp + MHA1(inp)) ---- (fine-grained weight waits)
    transpose_split<false><<<dim3(SEQ_/32, IN_/32), dim3(32,8)>>>(inp, B.xTh, B.xTl, IN_, SEQ_);
    wait_ev(evA);
    {
        const long long IM = (long long)IN_*MID_, SM = (long long)SEQ_*MID_,
                        SI = (long long)SEQ_*IN_;
        gemm_hmma<true,false,1><<<dim3(SEQ_/BN, IN_/BM, 3), 256, GSMEM>>>(
            W1s.wqh, W1s.wql, B.xTh, B.xTl, nullptr, B.qh, B.ql, nullptr,
            IN_, SEQ_, IN_, 0, (long long)IN_*IN_, 0, 0, 0, IS, 0, 1);
        wait_ev(evB);
        gemm_hmma<true,false,1><<<dim3(MID_/BN, IN_/BM, H_*3), 256, GSMEM>>>(
            B.qh, B.ql, W1s.W1h, W1s.W1l, nullptr, B.hbh, B.hbl, nullptr,
            IN_, MID_, SEQ_, 0, 0, IS,
            3LL*MID_*SEQ_, (long long)MID_*SEQ_, 3*IM, IM, 3);
        wait_ev(evC);
        cudaEventRecord(evG, 0);
        // v projection on s2
        cudaStreamWaitEvent(s2, evG, 0);
        gemm_hmma<false,false,1><<<dim3(SEQ_/BN, IN_/BM, H_), 256, GSMEM, s2>>>(
            B.hbh + 2*IM, B.hbl + 2*IM, W1s.W2h + 2*SM, W1s.W2l + 2*SM, nullptr, B.vh, B.vl, nullptr,
            IN_, SEQ_, MID_, 0, 3*IM, 0, 3*SM, 0, IS, 0, 1);
        cudaEventRecord(evH, s2);
        // qk path
        gemm_hmma<false,false,2><<<dim3(SEQ_/BN, IN_/BM, H_*2), 256, GSMEM>>>(
            B.hbh, B.hbl, W1s.W2h, W1s.W2l, nullptr, B.qkTh, B.qkTl, nullptr,
            IN_, SEQ_, MID_, IN_, 3*IM, IM, 3*SM, SM, SI, (long long)H_*SI, 2);
        gemm_hmma<false,false,1><<<dim3(SEQ_/BN, SEQ_/BM, H_), 256, GSMEM>>>(
            B.qkTh, B.qkTl, B.qkTh + (long long)H_*SI, B.qkTl + (long long)H_*SI,
            nullptr, B.bTh, B.bTl, nullptr,
            SEQ_, SEQ_, IN_, 0, SI, 0, SI, 0, (long long)SEQ_*SEQ_, 0, 1);
        wait_ev(evH);
        gemm_hmma<true,false,2><<<dim3(SEQ_/BN, IN_/BM, H_), 256, GSMEM>>>(
            B.vh, B.vl, B.bTh, B.bTl, nullptr, B.aTh, B.aTl, nullptr,
            IN_, SEQ_, SEQ_, H_*IN_, IS, 0, (long long)SEQ_*SEQ_, 0, IN_, 0, 1);
        wait_ev(evD);
        gemm_hmma<true,false,2><<<dim3(SEQ_/BN, MID_/BM, 1), 256, GSMEM>>>(
            W1s.c1h, W1s.c1l, B.aTh, B.aTl, nullptr, B.zTh, B.zTl, nullptr,
            MID_, SEQ_, H_*IN_, MID_, 0,0, 0,0, 0,0, 1);
        gemm_hmma<false,false,0><<<dim3(SEQ_/BN, IN_/BM, 1), 256, GSMEM>>>(
            W1s.c2h, W1s.c2l, B.zTh, B.zTl, B.mout,
            (__nv_bfloat16*)nullptr, (__nv_bfloat16*)nullptr, nullptr,
            IN_, SEQ_, MID_, 0, 0,0, 0,0, 0,0, 1);
    }
    add_ln_kernel<<<IN_, 256>>>(inp, B.mout, norm_w, norm_b, B.x1);

    // ---- Block 2: x2 = LN(inp + MHA2(x1)) ----
    transpose_split<false><<<dim3(SEQ_/32, IN_/32), dim3(32,8)>>>(B.x1, B.xTh, B.xTl, IN_, SEQ_);
    wait_ev(evE);
    launch_mha(W2s, B);
    add_ln_kernel<<<IN_, 256>>>(inp, B.mout, norm_w, norm_b, B.x2);

    // ---- Two FFN heads as z=2 batched GEMMs ----
    transpose_split<true><<<dim3(SEQ_/32, IN_/32), dim3(32,8)>>>(B.x2, B.xTh, B.xTl, IN_, SEQ_);
    wait_ev(evF);
    // zT[z] = splitT(relu(Wa[z] @ relu(x2)))       M=MID N=SEQ K=IN, z=2, OM=2
    gemm_hmma<true,false,2><<<dim3(SEQ_/BN, MID_/BM, 2), 256, GSMEM>>>(
        WaSh, WaSl, B.xTh, B.xTl, nullptr, B.zTh, B.zTl, nullptr,
        MID_, SEQ_, IN_, MID_,
        nWa, 0, 0, 0, (long long)SEQ_*MID_, 0, 1);
    // out[z] = Wb[z] @ relu(t[z]) + x2             M=IN N=SEQ K=MID, z=2, OM=0 RES (z-invariant)
    gemm_hmma<false,true,0><<<dim3(SEQ_/BN, IN_/BM, 2), 256, GSMEM>>>(
        WbSh, WbSl, B.zTh, B.zTl, out,
        (__nv_bfloat16*)nullptr, (__nv_bfloat16*)nullptr, B.x2,
        IN_, SEQ_, MID_, 0,
        nWb, 0, (long long)SEQ_*MID_, 0, IS, 0, 1);
}